// round 12
// baseline (speedup 1.0000x reference)
#include <cuda_runtime.h>
#include <cuda_fp16.h>
#include <cstdint>

#define N_NODES 100000
#define N_EDGES 3200000
#define F0 16
#define F1 32
#define F2 3
#define CAP 96   // max in-degree slots; Poisson(32) tail beyond 96 ~ 1e-18/node

// ---------------- scratch (no allocations allowed) ----------------
__device__ int g_is64;
__device__ static int   g_count[N_NODES];
__device__ static int   g_slots[N_NODES * CAP];               // 38.4 MB
__device__ __align__(16) static float  g_dinv[N_NODES];
__device__ __align__(16) static __half g_h1h [N_NODES * F1];  // h1 fp16 (scaled in phase 1)
__device__ __align__(16) static float  g_h2s4[N_NODES * 4];   // h2 * dinv, padded
__device__ int g_bar_count;
__device__ int g_bar_gen;

// ---------------- zero + dtype detect (fused) ----------------
__global__ void k_zero_detect(const int* __restrict__ ei32) {
    int i = blockIdx.x * blockDim.x + threadIdx.x;
    if (i < N_NODES) g_count[i] = 0;
    if (i == 0) {
        int any_nonzero = 0;
        for (int k = 0; k < 128; k++) any_nonzero |= ei32[2 * k + 1];
        g_is64 = (any_nonzero == 0) ? 1 : 0;
    }
}

// slot-table build, 2 edges per thread (vectorized index loads)
__global__ void k_fill(const void* __restrict__ ei) {
    int t = blockIdx.x * blockDim.x + threadIdx.x;
    int e = t * 2;
    if (e >= N_EDGES) return;
    int s0, d0, s1, d1;
    if (g_is64) {
        const longlong2* ps = (const longlong2*)((const long long*)ei + e);
        const longlong2* pd = (const longlong2*)((const long long*)ei + N_EDGES + e);
        longlong2 sv = *ps, dv = *pd;
        s0 = (int)sv.x; s1 = (int)sv.y;
        d0 = (int)dv.x; d1 = (int)dv.y;
    } else {
        const int2* ps = (const int2*)((const int*)ei + e);
        const int2* pd = (const int2*)((const int*)ei + N_EDGES + e);
        int2 sv = *ps, dv = *pd;
        s0 = sv.x; s1 = sv.y;
        d0 = dv.x; d1 = dv.y;
    }
    int slot0 = atomicAdd(&g_count[d0], 1);
    if (slot0 < CAP) g_slots[d0 * CAP + slot0] = s0;
    int slot1 = atomicAdd(&g_count[d1], 1);
    if (slot1 < CAP) g_slots[d1 * CAP + slot1] = s1;
}

// 2 threads per node, 16 output features each; UNSCALED fp16 h1
// (independent of counts -> overlaps k_fill on a second stream)
__global__ void k_layer1_gemm(const float* __restrict__ x,
                              const float* __restrict__ W1) {
    __shared__ float sW[F0 * F1];
    for (int t = threadIdx.x; t < F0 * F1; t += blockDim.x) sW[t] = W1[t];
    __syncthreads();

    int t = blockIdx.x * blockDim.x + threadIdx.x;
    int i = t >> 1;
    int hsel = t & 1;
    if (i >= N_NODES) return;

    float xv[F0];
    const float4* xr = (const float4*)(x + i * F0);
    #pragma unroll
    for (int k = 0; k < F0 / 4; k++) {
        float4 v = xr[k];
        xv[4*k+0] = v.x; xv[4*k+1] = v.y; xv[4*k+2] = v.z; xv[4*k+3] = v.w;
    }

    float acc[16];
    #pragma unroll
    for (int j = 0; j < 16; j++) acc[j] = 0.0f;
    const float* wbase = sW + hsel * 16;
    #pragma unroll
    for (int k = 0; k < F0; k++) {
        float xk = xv[k];
        #pragma unroll
        for (int j = 0; j < 16; j++) acc[j] = fmaf(xk, wbase[k * F1 + j], acc[j]);
    }

    __half2 o[8];
    #pragma unroll
    for (int j = 0; j < 8; j++)
        o[j] = __floats2half2_rn(acc[2*j], acc[2*j+1]);
    uint4* dst = (uint4*)(g_h1h + i * F1 + hsel * 16);
    dst[0] = *(const uint4*)&o[0];
    dst[1] = *(const uint4*)&o[4];
}

// -------- software grid barrier (sense-reversal via generation counter) -----
__device__ __forceinline__ void grid_barrier() {
    __syncthreads();
    if (threadIdx.x == 0) {
        __threadfence();
        int snap = *((volatile int*)&g_bar_gen);
        int old = atomicAdd(&g_bar_count, 1);
        if (old == (int)gridDim.x - 1) {
            atomicExch(&g_bar_count, 0);
            __threadfence();
            atomicAdd(&g_bar_gen, 1);
        } else {
            while (*((volatile int*)&g_bar_gen) == snap) { }
            __threadfence();
        }
    }
    __syncthreads();
}

// persistent fused kernel: phase1 scale+dinv | bar | phase2 agg1+layer2 | bar | phase3 agg2+softmax
__global__ void __launch_bounds__(256, 6)
k_fused(const float* __restrict__ W2, const float* __restrict__ b1,
        const float* __restrict__ b2, float* __restrict__ out) {
    const int nthreads = gridDim.x * blockDim.x;
    const int tid0 = blockIdx.x * blockDim.x + threadIdx.x;

    // ---- phase 1: dinv = rsqrt(count+1); scale h1 in place (2 items/node) ----
    for (int t = tid0; t < N_NODES * 2; t += nthreads) {
        int i = t >> 1;
        int hsel = t & 1;
        float di = rsqrtf((float)(g_count[i] + 1));
        if (hsel == 0) g_dinv[i] = di;
        uint4* p = (uint4*)(g_h1h + i * F1 + hsel * 16);
        #pragma unroll
        for (int q = 0; q < 2; q++) {
            uint4 u = p[q];
            __half2* h = (__half2*)&u;   // 4 half2 per uint4
            #pragma unroll
            for (int j = 0; j < 4; j++) {
                float2 f = __half22float2(h[j]);
                h[j] = __floats2half2_rn(f.x * di, f.y * di);
            }
            p[q] = u;
        }
    }

    grid_barrier();

    // ---- phase 2: warp-per-node aggregate + fused layer 2 ----
    {
        const int nwarps = nthreads >> 5;
        const int warp0 = tid0 >> 5;
        const int lane = threadIdx.x & 31;
        const int grp = lane >> 4;
        const int j = lane & 15;
        const __half2* h1 = (const __half2*)g_h1h;

        for (int i = warp0; i < N_NODES; i += nwarps) {
            int cnt = min(g_count[i], CAP);
            int row = i * CAP;
            float di = g_dinv[i];

            float2 acc = make_float2(0.0f, 0.0f);
            if (grp == 0) acc = __half22float2(h1[i * 16 + j]);   // self-loop (scaled)

            int k = 0;
            for (; k + 8 <= cnt; k += 8) {
                int b = row + k + 4 * grp;
                int s0 = g_slots[b + 0];
                int s1 = g_slots[b + 1];
                int s2 = g_slots[b + 2];
                int s3 = g_slots[b + 3];
                float2 f0 = __half22float2(h1[s0 * 16 + j]);
                float2 f1 = __half22float2(h1[s1 * 16 + j]);
                float2 f2 = __half22float2(h1[s2 * 16 + j]);
                float2 f3 = __half22float2(h1[s3 * 16 + j]);
                acc.x += (f0.x + f1.x) + (f2.x + f3.x);
                acc.y += (f0.y + f1.y) + (f2.y + f3.y);
            }
            for (int kk = k + grp; kk < cnt; kk += 2) {
                int s = g_slots[row + kk];
                float2 f = __half22float2(h1[s * 16 + j]);
                acc.x += f.x; acc.y += f.y;
            }
            acc.x += __shfl_xor_sync(0xFFFFFFFFu, acc.x, 16);
            acc.y += __shfl_xor_sync(0xFFFFFFFFu, acc.y, 16);

            float h0  = fmaxf(fmaf(di, acc.x, __ldg(&b1[2*j])),   0.0f);
            float h1v = fmaxf(fmaf(di, acc.y, __ldg(&b1[2*j+1])), 0.0f);
            float p0 = h0 * __ldg(&W2[(2*j)*F2+0]) + h1v * __ldg(&W2[(2*j+1)*F2+0]);
            float p1 = h0 * __ldg(&W2[(2*j)*F2+1]) + h1v * __ldg(&W2[(2*j+1)*F2+1]);
            float p2 = h0 * __ldg(&W2[(2*j)*F2+2]) + h1v * __ldg(&W2[(2*j+1)*F2+2]);
            #pragma unroll
            for (int off = 8; off > 0; off >>= 1) {
                p0 += __shfl_xor_sync(0xFFFFFFFFu, p0, off);
                p1 += __shfl_xor_sync(0xFFFFFFFFu, p1, off);
                p2 += __shfl_xor_sync(0xFFFFFFFFu, p2, off);
            }
            if (lane == 0) {
                float4 o;
                o.x = p0 * di; o.y = p1 * di; o.z = p2 * di; o.w = 0.0f;
                ((float4*)g_h2s4)[i] = o;
            }
        }
    }

    grid_barrier();

    // ---- phase 3: thread-per-node aggregate + bias + log_softmax ----
    for (int i = tid0; i < N_NODES; i += nthreads) {
        int cnt = min(g_count[i], CAP);
        int row = i * CAP;
        float di = g_dinv[i];

        float4 self = ((const float4*)g_h2s4)[i];
        float a0 = self.x, a1 = self.y, a2 = self.z;

        int k = 0;
        for (; k + 4 <= cnt; k += 4) {
            int s0 = g_slots[row + k + 0];
            int s1 = g_slots[row + k + 1];
            int s2 = g_slots[row + k + 2];
            int s3 = g_slots[row + k + 3];
            float4 v0 = ((const float4*)g_h2s4)[s0];
            float4 v1 = ((const float4*)g_h2s4)[s1];
            float4 v2 = ((const float4*)g_h2s4)[s2];
            float4 v3 = ((const float4*)g_h2s4)[s3];
            a0 += (v0.x + v1.x) + (v2.x + v3.x);
            a1 += (v0.y + v1.y) + (v2.y + v3.y);
            a2 += (v0.z + v1.z) + (v2.z + v3.z);
        }
        for (; k < cnt; k++) {
            float4 v = ((const float4*)g_h2s4)[g_slots[row + k]];
            a0 += v.x; a1 += v.y; a2 += v.z;
        }

        float v0 = fmaf(a0, di, __ldg(&b2[0]));
        float v1 = fmaf(a1, di, __ldg(&b2[1]));
        float v2 = fmaf(a2, di, __ldg(&b2[2]));
        float m = fmaxf(v0, fmaxf(v1, v2));
        float l = logf(expf(v0 - m) + expf(v1 - m) + expf(v2 - m));
        out[i * F2 + 0] = v0 - m - l;
        out[i * F2 + 1] = v1 - m - l;
        out[i * F2 + 2] = v2 - m - l;
    }
}

// ---------------- launch ----------------

extern "C" void kernel_launch(void* const* d_in, const int* in_sizes, int n_in,
                              void* d_out, int out_size) {
    const float* x  = (const float*)d_in[0];
    const void*  ei = d_in[1];
    const float* W1 = (const float*)d_in[2];
    const float* b1 = (const float*)d_in[3];
    const float* W2 = (const float*)d_in[4];
    const float* b2 = (const float*)d_in[5];
    float*       out = (float*)d_out;

    static cudaStream_t s2 = nullptr;
    static cudaEvent_t evFork = nullptr, evJoin = nullptr;
    static int fusedBlocks = 0;
    if (s2 == nullptr) {
        cudaStreamCreateWithFlags(&s2, cudaStreamNonBlocking);
        cudaEventCreateWithFlags(&evFork, cudaEventDisableTiming);
        cudaEventCreateWithFlags(&evJoin, cudaEventDisableTiming);
        int dev = 0, nsm = 0, bpm = 0;
        cudaGetDevice(&dev);
        cudaDeviceGetAttribute(&nsm, cudaDevAttrMultiProcessorCount, dev);
        cudaOccupancyMaxActiveBlocksPerMultiprocessor(&bpm, k_fused, 256, 0);
        if (bpm < 1) bpm = 1;
        if (nsm < 1) nsm = 148;
        fusedBlocks = nsm * bpm;       // guaranteed co-resident
    }

    const int T = 256;
    const int gN  = (N_NODES + T - 1) / T;               // 391
    const int gN2 = (N_NODES * 2 + T - 1) / T;           // 782
    const int gE2 = (N_EDGES / 2 + T - 1) / T;           // 6250

    k_zero_detect<<<gN, T>>>((const int*)ei);

    // fork: layer1 GEMM (independent of counts) overlaps the slot-table build
    cudaEventRecord(evFork, 0);
    cudaStreamWaitEvent(s2, evFork, 0);
    k_layer1_gemm<<<gN2, T, 0, s2>>>(x, W1);

    k_fill       <<<gE2, T>>>(ei);

    cudaEventRecord(evJoin, s2);
    cudaStreamWaitEvent(0, evJoin, 0);

    k_fused      <<<fusedBlocks, T>>>(W2, b1, b2, out);
}

// round 13
// speedup vs baseline: 1.1159x; 1.1159x over previous
#include <cuda_runtime.h>
#include <cuda_fp16.h>
#include <cstdint>

#define N_NODES 100000
#define N_EDGES 3200000
#define F0 16
#define F1 32
#define F2 3
#define CAP 96   // max in-degree slots; Poisson(32) tail beyond 96 ~ 1e-18/node

// ---------------- scratch (no allocations allowed) ----------------
// g_count starts BSS-zeroed; k_scale re-zeros it for the next call.
__device__ static int   g_count[N_NODES];
__device__ static int   g_cnt2 [N_NODES];
__device__ static int   g_slots[N_NODES * CAP];               // 38.4 MB
__device__ __align__(16) static float  g_dinv[N_NODES];
__device__ __align__(16) static __half g_h1h [N_NODES * F1];  // h1 fp16 (scaled by k_scale)
__device__ __align__(16) static float  g_h2s4[N_NODES * 4];   // h2 * dinv, padded

// slot-table build, 4 edges per thread; dtype detected inline per-thread
// from the first cache line (broadcast loads, ~free).
__global__ void k_fill(const void* __restrict__ ei) {
    const int* e32 = (const int*)ei;
    // int64 ids < 2^31 => odd words zero; int32 random ids => P(all zero) ~ 1e-20
    bool is64 = ((e32[1] | e32[3] | e32[5] | e32[7]) == 0);

    int t = blockIdx.x * blockDim.x + threadIdx.x;
    int e = t * 4;
    if (e >= N_EDGES) return;

    int s[4], d[4];
    if (is64) {
        const long long* p = (const long long*)ei;
        longlong2 sv0 = *(const longlong2*)(p + e);
        longlong2 sv1 = *(const longlong2*)(p + e + 2);
        longlong2 dv0 = *(const longlong2*)(p + N_EDGES + e);
        longlong2 dv1 = *(const longlong2*)(p + N_EDGES + e + 2);
        s[0] = (int)sv0.x; s[1] = (int)sv0.y; s[2] = (int)sv1.x; s[3] = (int)sv1.y;
        d[0] = (int)dv0.x; d[1] = (int)dv0.y; d[2] = (int)dv1.x; d[3] = (int)dv1.y;
    } else {
        int4 sv = *(const int4*)(e32 + e);
        int4 dv = *(const int4*)(e32 + N_EDGES + e);
        s[0] = sv.x; s[1] = sv.y; s[2] = sv.z; s[3] = sv.w;
        d[0] = dv.x; d[1] = dv.y; d[2] = dv.z; d[3] = dv.w;
    }
    #pragma unroll
    for (int q = 0; q < 4; q++) {
        int slot = atomicAdd(&g_count[d[q]], 1);
        if (slot < CAP) g_slots[d[q] * CAP + slot] = s[q];
    }
}

// 2 threads per node, 16 output features each; UNSCALED fp16 h1.
// Depends only on inputs -> forked at t=0, hides under k_fill.
__global__ void k_layer1_gemm(const float* __restrict__ x,
                              const float* __restrict__ W1) {
    __shared__ float sW[F0 * F1];
    for (int t = threadIdx.x; t < F0 * F1; t += blockDim.x) sW[t] = W1[t];
    __syncthreads();

    int t = blockIdx.x * blockDim.x + threadIdx.x;
    int i = t >> 1;
    int hsel = t & 1;
    if (i >= N_NODES) return;

    float xv[F0];
    const float4* xr = (const float4*)(x + i * F0);
    #pragma unroll
    for (int k = 0; k < F0 / 4; k++) {
        float4 v = xr[k];
        xv[4*k+0] = v.x; xv[4*k+1] = v.y; xv[4*k+2] = v.z; xv[4*k+3] = v.w;
    }

    float acc[16];
    #pragma unroll
    for (int j = 0; j < 16; j++) acc[j] = 0.0f;
    const float* wbase = sW + hsel * 16;
    #pragma unroll
    for (int k = 0; k < F0; k++) {
        float xk = xv[k];
        #pragma unroll
        for (int j = 0; j < 16; j++) acc[j] = fmaf(xk, wbase[k * F1 + j], acc[j]);
    }

    __half2 o[8];
    #pragma unroll
    for (int j = 0; j < 8; j++)
        o[j] = __floats2half2_rn(acc[2*j], acc[2*j+1]);
    uint4* dst = (uint4*)(g_h1h + i * F1 + hsel * 16);
    dst[0] = *(const uint4*)&o[0];
    dst[1] = *(const uint4*)&o[4];
}

// dinv = rsqrt(count+1); scale h1 in place; copy count to g_cnt2 and
// zero g_count for the next call (BSS gives zeros on the very first call).
// 2 threads per node (16 halves = 2 uint4 each).
__global__ void k_scale() {
    int t = blockIdx.x * blockDim.x + threadIdx.x;
    int i = t >> 1;
    int hsel = t & 1;
    if (i >= N_NODES) return;

    int cnt = g_count[i];
    float di = rsqrtf((float)(cnt + 1));
    if (hsel == 0) {
        g_dinv[i] = di;
        g_cnt2[i] = cnt;
        g_count[i] = 0;        // ready for next call
    }

    uint4* p = (uint4*)(g_h1h + i * F1 + hsel * 16);
    #pragma unroll
    for (int q = 0; q < 2; q++) {
        uint4 u = p[q];
        __half2* h = (__half2*)&u;   // 4 half2 per uint4
        #pragma unroll
        for (int j = 0; j < 4; j++) {
            float2 f = __half22float2(h[j]);
            h[j] = __floats2half2_rn(f.x * di, f.y * di);
        }
        p[q] = u;
    }
}

// warp per node: two 16-lane groups, 4 contiguous edges per step (R10 hot loop)
__global__ void k_agg1_fused(const float* __restrict__ W2,
                             const float* __restrict__ b1) {
    int warp = (blockIdx.x * blockDim.x + threadIdx.x) >> 5;
    int lane = threadIdx.x & 31;
    if (warp >= N_NODES) return;
    int i = warp;

    int cnt = min(g_cnt2[i], CAP);
    int row = i * CAP;
    float di = g_dinv[i];
    int grp = lane >> 4;
    int j   = lane & 15;

    const __half2* h1 = (const __half2*)g_h1h;

    float2 acc = make_float2(0.0f, 0.0f);
    if (grp == 0) acc = __half22float2(h1[i * 16 + j]);   // self-loop (pre-scaled)

    int k = 0;
    for (; k + 8 <= cnt; k += 8) {
        int b = row + k + 4 * grp;
        int s0 = g_slots[b + 0];
        int s1 = g_slots[b + 1];
        int s2 = g_slots[b + 2];
        int s3 = g_slots[b + 3];
        float2 f0 = __half22float2(h1[s0 * 16 + j]);
        float2 f1 = __half22float2(h1[s1 * 16 + j]);
        float2 f2 = __half22float2(h1[s2 * 16 + j]);
        float2 f3 = __half22float2(h1[s3 * 16 + j]);
        acc.x += (f0.x + f1.x) + (f2.x + f3.x);
        acc.y += (f0.y + f1.y) + (f2.y + f3.y);
    }
    for (int kk = k + grp; kk < cnt; kk += 2) {
        int s = g_slots[row + kk];
        float2 f = __half22float2(h1[s * 16 + j]);
        acc.x += f.x; acc.y += f.y;
    }
    acc.x += __shfl_xor_sync(0xFFFFFFFFu, acc.x, 16);
    acc.y += __shfl_xor_sync(0xFFFFFFFFu, acc.y, 16);

    float h0  = fmaxf(fmaf(di, acc.x, __ldg(&b1[2*j])),   0.0f);
    float h1v = fmaxf(fmaf(di, acc.y, __ldg(&b1[2*j+1])), 0.0f);
    float p0 = h0 * __ldg(&W2[(2*j)*F2+0]) + h1v * __ldg(&W2[(2*j+1)*F2+0]);
    float p1 = h0 * __ldg(&W2[(2*j)*F2+1]) + h1v * __ldg(&W2[(2*j+1)*F2+1]);
    float p2 = h0 * __ldg(&W2[(2*j)*F2+2]) + h1v * __ldg(&W2[(2*j+1)*F2+2]);
    #pragma unroll
    for (int off = 8; off > 0; off >>= 1) {
        p0 += __shfl_xor_sync(0xFFFFFFFFu, p0, off);
        p1 += __shfl_xor_sync(0xFFFFFFFFu, p1, off);
        p2 += __shfl_xor_sync(0xFFFFFFFFu, p2, off);
    }
    if (lane == 0) {
        float4 o;
        o.x = p0 * di; o.y = p1 * di; o.z = p2 * di; o.w = 0.0f;
        ((float4*)g_h2s4)[i] = o;
    }
}

// thread per node: aggregate h2s4 + self, bias, log_softmax (R10 hot loop)
__global__ void k_agg2_fused(const float* __restrict__ b2,
                             float* __restrict__ out) {
    int i = blockIdx.x * blockDim.x + threadIdx.x;
    if (i >= N_NODES) return;

    int cnt = min(g_cnt2[i], CAP);
    int row = i * CAP;
    float di = g_dinv[i];

    float4 self = ((const float4*)g_h2s4)[i];
    float a0 = self.x, a1 = self.y, a2 = self.z;

    int k = 0;
    for (; k + 4 <= cnt; k += 4) {
        int s0 = g_slots[row + k + 0];
        int s1 = g_slots[row + k + 1];
        int s2 = g_slots[row + k + 2];
        int s3 = g_slots[row + k + 3];
        float4 v0 = ((const float4*)g_h2s4)[s0];
        float4 v1 = ((const float4*)g_h2s4)[s1];
        float4 v2 = ((const float4*)g_h2s4)[s2];
        float4 v3 = ((const float4*)g_h2s4)[s3];
        a0 += (v0.x + v1.x) + (v2.x + v3.x);
        a1 += (v0.y + v1.y) + (v2.y + v3.y);
        a2 += (v0.z + v1.z) + (v2.z + v3.z);
    }
    for (; k < cnt; k++) {
        float4 v = ((const float4*)g_h2s4)[g_slots[row + k]];
        a0 += v.x; a1 += v.y; a2 += v.z;
    }

    float v0 = fmaf(a0, di, __ldg(&b2[0]));
    float v1 = fmaf(a1, di, __ldg(&b2[1]));
    float v2 = fmaf(a2, di, __ldg(&b2[2]));
    float m = fmaxf(v0, fmaxf(v1, v2));
    float l = logf(expf(v0 - m) + expf(v1 - m) + expf(v2 - m));
    out[i * F2 + 0] = v0 - m - l;
    out[i * F2 + 1] = v1 - m - l;
    out[i * F2 + 2] = v2 - m - l;
}

// ---------------- launch ----------------

extern "C" void kernel_launch(void* const* d_in, const int* in_sizes, int n_in,
                              void* d_out, int out_size) {
    const float* x  = (const float*)d_in[0];
    const void*  ei = d_in[1];
    const float* W1 = (const float*)d_in[2];
    const float* b1 = (const float*)d_in[3];
    const float* W2 = (const float*)d_in[4];
    const float* b2 = (const float*)d_in[5];
    float*       out = (float*)d_out;

    static cudaStream_t s2 = nullptr;
    static cudaEvent_t evFork = nullptr, evJoin = nullptr;
    if (s2 == nullptr) {
        cudaStreamCreateWithFlags(&s2, cudaStreamNonBlocking);
        cudaEventCreateWithFlags(&evFork, cudaEventDisableTiming);
        cudaEventCreateWithFlags(&evJoin, cudaEventDisableTiming);
    }

    const int T = 256;
    const int gN  = (N_NODES + T - 1) / T;               // 391
    const int gN2 = (N_NODES * 2 + T - 1) / T;           // 782
    const int gE4 = (N_EDGES / 4 + T - 1) / T;           // 3125
    const int gW  = (N_NODES * 32 + T - 1) / T;          // warp per node

    // fork at t=0: layer1 GEMM is independent of everything but inputs
    cudaEventRecord(evFork, 0);
    cudaStreamWaitEvent(s2, evFork, 0);
    k_layer1_gemm<<<gN2, T, 0, s2>>>(x, W1);

    k_fill       <<<gE4, T>>>(ei);

    cudaEventRecord(evJoin, s2);
    cudaStreamWaitEvent(0, evJoin, 0);

    k_scale      <<<gN2, T>>>();
    k_agg1_fused <<<gW, T>>>(W2, b1);
    k_agg2_fused <<<gN, T>>>(b2, out);
}

// round 14
// speedup vs baseline: 1.1481x; 1.0289x over previous
#include <cuda_runtime.h>
#include <cuda_fp16.h>
#include <cstdint>

#define N_NODES 100000
#define N_EDGES 3200000
#define F0 16
#define F1 32
#define F2 3
#define CAP 96   // max in-degree slots; Poisson(32) tail beyond 96 ~ 1e-18/node

// ---------------- scratch (no allocations allowed) ----------------
// g_count starts BSS-zeroed; k_scale re-zeros it for the next call.
__device__ static int   g_count[N_NODES];
__device__ static int   g_cnt2 [N_NODES];
__device__ static int   g_slots[N_NODES * CAP];               // 38.4 MB
__device__ __align__(16) static float  g_dinv[N_NODES];
__device__ __align__(16) static __half g_h1h [N_NODES * F1];  // h1 fp16 (scaled by k_scale)
__device__ __align__(16) static float  g_h2s4[N_NODES * 4];   // h2 * dinv, padded

// slot-table build, 4 edges per thread; dtype detected inline per-thread
__global__ void k_fill(const void* __restrict__ ei) {
    const int* e32 = (const int*)ei;
    // int64 ids < 2^31 => odd words zero; int32 random ids => P(all zero) ~ 1e-20
    bool is64 = ((e32[1] | e32[3] | e32[5] | e32[7]) == 0);

    int t = blockIdx.x * blockDim.x + threadIdx.x;
    int e = t * 4;
    if (e >= N_EDGES) return;

    int s[4], d[4];
    if (is64) {
        const long long* p = (const long long*)ei;
        longlong2 sv0 = *(const longlong2*)(p + e);
        longlong2 sv1 = *(const longlong2*)(p + e + 2);
        longlong2 dv0 = *(const longlong2*)(p + N_EDGES + e);
        longlong2 dv1 = *(const longlong2*)(p + N_EDGES + e + 2);
        s[0] = (int)sv0.x; s[1] = (int)sv0.y; s[2] = (int)sv1.x; s[3] = (int)sv1.y;
        d[0] = (int)dv0.x; d[1] = (int)dv0.y; d[2] = (int)dv1.x; d[3] = (int)dv1.y;
    } else {
        int4 sv = *(const int4*)(e32 + e);
        int4 dv = *(const int4*)(e32 + N_EDGES + e);
        s[0] = sv.x; s[1] = sv.y; s[2] = sv.z; s[3] = sv.w;
        d[0] = dv.x; d[1] = dv.y; d[2] = dv.z; d[3] = dv.w;
    }
    #pragma unroll
    for (int q = 0; q < 4; q++) {
        int slot = atomicAdd(&g_count[d[q]], 1);
        if (slot < CAP) g_slots[d[q] * CAP + slot] = s[q];
    }
}

// 2 threads per node, 16 output features each; UNSCALED fp16 h1.
// Depends only on inputs -> forked at t=0, hides under k_fill.
__global__ void k_layer1_gemm(const float* __restrict__ x,
                              const float* __restrict__ W1) {
    __shared__ float sW[F0 * F1];
    for (int t = threadIdx.x; t < F0 * F1; t += blockDim.x) sW[t] = W1[t];
    __syncthreads();

    int t = blockIdx.x * blockDim.x + threadIdx.x;
    int i = t >> 1;
    int hsel = t & 1;
    if (i >= N_NODES) return;

    float xv[F0];
    const float4* xr = (const float4*)(x + i * F0);
    #pragma unroll
    for (int k = 0; k < F0 / 4; k++) {
        float4 v = xr[k];
        xv[4*k+0] = v.x; xv[4*k+1] = v.y; xv[4*k+2] = v.z; xv[4*k+3] = v.w;
    }

    float acc[16];
    #pragma unroll
    for (int j = 0; j < 16; j++) acc[j] = 0.0f;
    const float* wbase = sW + hsel * 16;
    #pragma unroll
    for (int k = 0; k < F0; k++) {
        float xk = xv[k];
        #pragma unroll
        for (int j = 0; j < 16; j++) acc[j] = fmaf(xk, wbase[k * F1 + j], acc[j]);
    }

    __half2 o[8];
    #pragma unroll
    for (int j = 0; j < 8; j++)
        o[j] = __floats2half2_rn(acc[2*j], acc[2*j+1]);
    uint4* dst = (uint4*)(g_h1h + i * F1 + hsel * 16);
    dst[0] = *(const uint4*)&o[0];
    dst[1] = *(const uint4*)&o[4];
}

// dinv = rsqrt(count+1); scale h1 in place; copy count to g_cnt2 and
// zero g_count for the next call (BSS gives zeros on the very first call).
__global__ void k_scale() {
    int t = blockIdx.x * blockDim.x + threadIdx.x;
    int i = t >> 1;
    int hsel = t & 1;
    if (i >= N_NODES) return;

    int cnt = g_count[i];
    float di = rsqrtf((float)(cnt + 1));
    if (hsel == 0) {
        g_dinv[i] = di;
        g_cnt2[i] = cnt;
        g_count[i] = 0;        // ready for next call
    }

    uint4* p = (uint4*)(g_h1h + i * F1 + hsel * 16);
    #pragma unroll
    for (int q = 0; q < 2; q++) {
        uint4 u = p[q];
        __half2* h = (__half2*)&u;   // 4 half2 per uint4
        #pragma unroll
        for (int j = 0; j < 4; j++) {
            float2 f = __half22float2(h[j]);
            h[j] = __floats2half2_rn(f.x * di, f.y * di);
        }
        p[q] = u;
    }
}

// warp per node: two 16-lane groups, 4 contiguous edges per step.
// Chunked fp16 accumulation (HADD2 tree) + one fp32 flush per chunk
// cuts per-edge instruction count ~32% (agg1 is issue-bound per R13 ncu).
__global__ void k_agg1_fused(const float* __restrict__ W2,
                             const float* __restrict__ b1) {
    int warp = (blockIdx.x * blockDim.x + threadIdx.x) >> 5;
    int lane = threadIdx.x & 31;
    if (warp >= N_NODES) return;
    int i = warp;

    int cnt = min(g_cnt2[i], CAP);
    int row = i * CAP;
    float di = g_dinv[i];
    int grp = lane >> 4;
    int j   = lane & 15;

    const __half2* h1 = (const __half2*)g_h1h;

    float2 acc = make_float2(0.0f, 0.0f);
    if (grp == 0) acc = __half22float2(h1[i * 16 + j]);   // self-loop (pre-scaled)

    int k = 0;
    for (; k + 8 <= cnt; k += 8) {
        int b = row + k + 4 * grp;
        int s0 = g_slots[b + 0];
        int s1 = g_slots[b + 1];
        int s2 = g_slots[b + 2];
        int s3 = g_slots[b + 3];
        __half2 ha = __hadd2(h1[s0 * 16 + j], h1[s1 * 16 + j]);
        __half2 hb = __hadd2(h1[s2 * 16 + j], h1[s3 * 16 + j]);
        float2 f = __half22float2(__hadd2(ha, hb));
        acc.x += f.x; acc.y += f.y;
    }
    for (int kk = k + grp; kk < cnt; kk += 2) {
        int s = g_slots[row + kk];
        float2 f = __half22float2(h1[s * 16 + j]);
        acc.x += f.x; acc.y += f.y;
    }
    acc.x += __shfl_xor_sync(0xFFFFFFFFu, acc.x, 16);
    acc.y += __shfl_xor_sync(0xFFFFFFFFu, acc.y, 16);

    float h0  = fmaxf(fmaf(di, acc.x, __ldg(&b1[2*j])),   0.0f);
    float h1v = fmaxf(fmaf(di, acc.y, __ldg(&b1[2*j+1])), 0.0f);
    float p0 = h0 * __ldg(&W2[(2*j)*F2+0]) + h1v * __ldg(&W2[(2*j+1)*F2+0]);
    float p1 = h0 * __ldg(&W2[(2*j)*F2+1]) + h1v * __ldg(&W2[(2*j+1)*F2+1]);
    float p2 = h0 * __ldg(&W2[(2*j)*F2+2]) + h1v * __ldg(&W2[(2*j+1)*F2+2]);
    #pragma unroll
    for (int off = 8; off > 0; off >>= 1) {
        p0 += __shfl_xor_sync(0xFFFFFFFFu, p0, off);
        p1 += __shfl_xor_sync(0xFFFFFFFFu, p1, off);
        p2 += __shfl_xor_sync(0xFFFFFFFFu, p2, off);
    }
    if (lane == 0) {
        float4 o;
        o.x = p0 * di; o.y = p1 * di; o.z = p2 * di; o.w = 0.0f;
        ((float4*)g_h2s4)[i] = o;
    }
}

// thread per node: aggregate h2s4 + self, bias, log_softmax
__global__ void k_agg2_fused(const float* __restrict__ b2,
                             float* __restrict__ out) {
    int i = blockIdx.x * blockDim.x + threadIdx.x;
    if (i >= N_NODES) return;

    int cnt = min(g_cnt2[i], CAP);
    int row = i * CAP;
    float di = g_dinv[i];

    float4 self = ((const float4*)g_h2s4)[i];
    float a0 = self.x, a1 = self.y, a2 = self.z;

    int k = 0;
    for (; k + 4 <= cnt; k += 4) {
        int s0 = g_slots[row + k + 0];
        int s1 = g_slots[row + k + 1];
        int s2 = g_slots[row + k + 2];
        int s3 = g_slots[row + k + 3];
        float4 v0 = ((const float4*)g_h2s4)[s0];
        float4 v1 = ((const float4*)g_h2s4)[s1];
        float4 v2 = ((const float4*)g_h2s4)[s2];
        float4 v3 = ((const float4*)g_h2s4)[s3];
        a0 += (v0.x + v1.x) + (v2.x + v3.x);
        a1 += (v0.y + v1.y) + (v2.y + v3.y);
        a2 += (v0.z + v1.z) + (v2.z + v3.z);
    }
    for (; k < cnt; k++) {
        float4 v = ((const float4*)g_h2s4)[g_slots[row + k]];
        a0 += v.x; a1 += v.y; a2 += v.z;
    }

    float v0 = fmaf(a0, di, __ldg(&b2[0]));
    float v1 = fmaf(a1, di, __ldg(&b2[1]));
    float v2 = fmaf(a2, di, __ldg(&b2[2]));
    float m = fmaxf(v0, fmaxf(v1, v2));
    float l = logf(expf(v0 - m) + expf(v1 - m) + expf(v2 - m));
    out[i * F2 + 0] = v0 - m - l;
    out[i * F2 + 1] = v1 - m - l;
    out[i * F2 + 2] = v2 - m - l;
}

// ---------------- launch ----------------

extern "C" void kernel_launch(void* const* d_in, const int* in_sizes, int n_in,
                              void* d_out, int out_size) {
    const float* x  = (const float*)d_in[0];
    const void*  ei = d_in[1];
    const float* W1 = (const float*)d_in[2];
    const float* b1 = (const float*)d_in[3];
    const float* W2 = (const float*)d_in[4];
    const float* b2 = (const float*)d_in[5];
    float*       out = (float*)d_out;

    static cudaStream_t s2 = nullptr;
    static cudaEvent_t evFork = nullptr, evJoin = nullptr;
    if (s2 == nullptr) {
        cudaStreamCreateWithFlags(&s2, cudaStreamNonBlocking);
        cudaEventCreateWithFlags(&evFork, cudaEventDisableTiming);
        cudaEventCreateWithFlags(&evJoin, cudaEventDisableTiming);
    }

    const int T = 256;
    const int gN  = (N_NODES + T - 1) / T;               // 391
    const int gN2 = (N_NODES * 2 + T - 1) / T;           // 782
    const int gE4 = (N_EDGES / 4 + T - 1) / T;           // 3125
    const int gW  = (N_NODES * 32 + T - 1) / T;          // warp per node

    // fork at t=0: layer1 GEMM is independent of everything but inputs
    cudaEventRecord(evFork, 0);
    cudaStreamWaitEvent(s2, evFork, 0);
    k_layer1_gemm<<<gN2, T, 0, s2>>>(x, W1);

    k_fill       <<<gE4, T>>>(ei);

    cudaEventRecord(evJoin, s2);
    cudaStreamWaitEvent(0, evJoin, 0);

    k_scale      <<<gN2, T>>>();
    k_agg1_fused <<<gW, T>>>(W2, b1);
    k_agg2_fused <<<gN, T>>>(b2, out);
}